// round 12
// baseline (speedup 1.0000x reference)
#include <cuda_runtime.h>
#include <math.h>

#define NS 64          // coarse samples
#define NF 128         // fine samples
#define NC 192         // combined
#define WPB 8          // warps per block
#define FULL 0xffffffffu

// #{k in [0,128) : u_k < x}, u_k = 0.05 + k * (0.9/127)
__device__ __forceinline__ int count_u(float x) {
    int c = __float2int_ru((x - 0.05f) * (127.0f / 0.9f));
    return min(max(c, 0), NF);
}

__device__ __forceinline__ unsigned long long pack2(float lo, float hi) {
    unsigned long long r;
    asm("mov.b64 %0, {%1, %2};" : "=l"(r) : "f"(lo), "f"(hi));
    return r;
}
__device__ __forceinline__ void unpack2(unsigned long long v, float& lo, float& hi) {
    asm("mov.b64 {%0, %1}, %2;" : "=f"(lo), "=f"(hi) : "l"(v));
}
__device__ __forceinline__ unsigned long long addp(unsigned long long a, unsigned long long b) {
    unsigned long long r;
    asm("add.rn.f32x2 %0, %1, %2;" : "=l"(r) : "l"(a), "l"(b));
    return r;
}

__global__ __launch_bounds__(WPB * 32, 8)
void pdf_sampler_kernel(const float* __restrict__ near_, const float* __restrict__ far_,
                        const float* __restrict__ density, const float* __restrict__ rgb,
                        float* __restrict__ zs_out, float* __restrict__ rgb_out,
                        float* __restrict__ depth_out, float* __restrict__ acc_out,
                        int B)
{
    __shared__ __align__(16) float  s_z[WPB][NC];        // staging; first 128B alias byte-S[]
    __shared__ __align__(16) float2 s_par[WPB][NS + 2];  // (cb, g) per interval, + tail

    const int warp = threadIdx.x >> 5;
    const int lane = threadIdx.x & 31;
    const int ray  = blockIdx.x * WPB + warp;
    if (ray >= B) return;

    const float nr = near_[ray];
    const float fr = far_[ray];
    const float delta = (fr - nr) * (1.0f / NS);

    // ---- density: 2 elems per lane, coalesced float2 ----
    const float2 dv = *reinterpret_cast<const float2*>(density + (size_t)ray * NS + 2 * lane);
    const float e0 = dv.x * delta;
    const float e1 = dv.y * delta;

    // ---- warp inclusive prefix sum of optical depth (pair per lane) ----
    const float ps = e0 + e1;
    float s = ps;
    #pragma unroll
    for (int off = 1; off < 32; off <<= 1) {
        float v = __shfl_up_sync(FULL, s, off);
        if (lane >= off) s += v;
    }
    const float excl = s - ps;           // cum optical depth before elem 2*lane

    // weights: 3 exps, rest by identity
    const float T0 = __expf(-excl);
    const float w0 = T0 * (1.0f - __expf(-e0));
    const float Tm = T0 - w0;            // = exp(-cum at 2*lane)
    const float w1 = Tm * (1.0f - __expf(-e1));
    const float Te = Tm - w1;            // = exp(-cum at 2*lane+1)

    // analytic mids
    const float m0 = fmaf((float)(2 * lane) + 0.5f, delta, nr);
    const float m1 = m0 + delta;

    // ---- rgb loads (6 contiguous floats per lane, coalesced) ----
    const float* rrow = rgb + (size_t)ray * (NS * 3) + 6 * lane;
    const float2 ra = *reinterpret_cast<const float2*>(rrow + 0);
    const float2 rb = *reinterpret_cast<const float2*>(rrow + 2);
    const float2 rc = *reinterpret_cast<const float2*>(rrow + 4);

    // ---- reductions (packed f32x2 butterflies): (rs,gs) and (bs,dsum) ----
    unsigned long long q0 = pack2(w0 * ra.x + w1 * rb.y,   // rs
                                  w0 * ra.y + w1 * rc.x);  // gs
    unsigned long long q1 = pack2(w0 * rb.x + w1 * rc.y,   // bs
                                  w0 * m0   + w1 * m1);    // dsum
    #pragma unroll
    for (int off = 16; off >= 1; off >>= 1) {
        q0 = addp(q0, __shfl_xor_sync(FULL, q0, off));
        q1 = addp(q1, __shfl_xor_sync(FULL, q1, off));
    }

    // total weight: exp(-ctot) is lane 31's Te
    const float wsum = 1.0f - __shfl_sync(FULL, Te, 31);
    const float inv  = __fdividef(1.0f, wsum + 1e-6f);

    // normalized cdf at this lane's two positions
    const float cd0 = (1.0f - Tm) * inv;   // cdf[2*lane]
    const float cd1 = (1.0f - Te) * inv;   // cdf[2*lane+1]
    float cprev = __shfl_up_sync(FULL, cd1, 1);   // cdf[2*lane-1]
    if (lane == 0) cprev = 0.0f;

    // interval boundaries in fine-sample index space
    const int kS = count_u(cprev);   // start of interval i0
    const int kM = count_u(cd0);     // start of interval i1 (= end of i0)
    const int kE = count_u(cd1);     // end of interval i1

    const int i0 = 2 * lane;
    const int i1 = i0 + 1;

    // per-interval affine params: z = fmaf(u - cb, g, mids[pc-1])
    const float dA  = cd0 - cprev;
    const float rdA = (dA < 1e-5f) ? 1.0f : __fdividef(1.0f, dA);
    const float gA  = (i0 == 0) ? 0.0f : rdA * delta;   // p=0: z = mids[0]
    const float dB  = cd1 - cd0;
    const float rdB = (dB < 1e-5f) ? 1.0f : __fdividef(1.0f, dB);
    const float gB  = rdB * delta;

    float* zw = s_z[warp];
    unsigned char* Sw = reinterpret_cast<unsigned char*>(zw);  // byte S[128] aliases staging
    float2* pw = s_par[warp];

    // ---- S init (1 STS.32/lane) + params (1 STS.128/lane, conflict-free) ----
    reinterpret_cast<int*>(zw)[lane] = 0;
    reinterpret_cast<float4*>(pw)[lane] = make_float4(cprev, gA, cd0, gB);  // pw[2l], pw[2l+1]
    if (lane == 31) pw[NS] = make_float2(0.0f, 0.0f);   // tail p=64: z = mids[63]
    __syncwarp();
    // interval-start marks (nonempty intervals have distinct starts; byte values 0..64)
    if (kS < kM) Sw[kS] = (unsigned char)i0;
    if (kM < kE) Sw[kM] = (unsigned char)i1;
    if (lane == 31 && kE < NF) Sw[kE] = (unsigned char)NS;   // tail interval start
    __syncwarp();

    // ---- p(k) = inclusive max-scan of byte S (1 LDS.32/lane) ----
    const unsigned int cwd = reinterpret_cast<const unsigned int*>(zw)[lane];
    const int s0 = (int)(cwd & 0xFF);
    const int s1 = max((int)((cwd >> 8)  & 0xFF), s0);
    const int s2 = max((int)((cwd >> 16) & 0xFF), s1);
    const int s3 = max((int)((cwd >> 24) & 0xFF), s2);
    int m = s3;
    #pragma unroll
    for (int off = 1; off < 32; off <<= 1) {
        int t = __shfl_up_sync(FULL, m, off);
        if (lane >= off) m = max(m, t);
    }
    int pex = __shfl_up_sync(FULL, m, 1);
    if (lane == 0) pex = 0;
    __syncwarp();   // S fully consumed; staging reuse begins

    // ---- balanced fine pass: 4 samples per lane, branch-free ----
    const float ustep = 0.9f / 127.0f;
    const float base  = nr - 0.5f * delta;       // mids[pc-1] = fmaf(pc, delta, base)
    const int pk0 = max(pex, s0), pk1 = max(pex, s1);
    const int pk2 = max(pex, s2), pk3 = max(pex, s3);
    #pragma unroll
    for (int j = 0; j < 4; ++j) {
        const int k = 4 * lane + j;
        const int p = (j == 0) ? pk0 : (j == 1) ? pk1 : (j == 2) ? pk2 : pk3;
        const int pc = min(max(p, 1), NS);       // clamp(p,1,64)
        const float2 pr = pw[p];
        const float u  = fmaf((float)k, ustep, 0.05f);
        const float mb = fmaf((float)pc, delta, base);
        zw[k + pc] = fmaf(u - pr.x, pr.y, mb);   // slot = k + clamp(p,1,64)
    }

    // ---- mids: slot = i + (# fine strictly before mid i) ----
    zw[(i0 == 0) ? 0 : (i0 + kM)] = m0;
    zw[i1 + kE] = m1;
    __syncwarp();

    // ---- coalesced vectorized write of the merged row ----
    float4* zv = reinterpret_cast<float4*>(zs_out + (size_t)ray * NC);
    const float4* sv = reinterpret_cast<const float4*>(zw);
    zv[lane] = sv[lane];                             // 128 floats
    if (lane < 16) zv[32 + lane] = sv[32 + lane];    // remaining 64

    // ---- scalar outputs, distributed ----
    if (lane < 5) {
        float rs, gs, bs, dsum;
        unpack2(q0, rs, gs);
        unpack2(q1, bs, dsum);
        if (lane < 3) {
            const float val = (lane == 0) ? rs : (lane == 1) ? gs : bs;
            rgb_out[(size_t)ray * 3 + lane] = val;
        } else if (lane == 3) {
            depth_out[ray] = __fdividef(dsum, wsum + 1e-8f);
        } else {
            acc_out[ray] = wsum;
        }
    }
}

extern "C" void kernel_launch(void* const* d_in, const int* in_sizes, int n_in,
                              void* d_out, int out_size)
{
    const float* near_   = (const float*)d_in[0];
    const float* far_    = (const float*)d_in[1];
    const float* density = (const float*)d_in[2];
    const float* rgb     = (const float*)d_in[3];
    const int B = in_sizes[0];

    float* out   = (float*)d_out;
    float* zs    = out;                       // B * 192
    float* rgbo  = zs + (size_t)B * NC;       // B * 3
    float* depth = rgbo + (size_t)B * 3;      // B
    float* acc   = depth + B;                 // B

    const int blocks = (B + WPB - 1) / WPB;
    pdf_sampler_kernel<<<blocks, WPB * 32>>>(near_, far_, density, rgb,
                                             zs, rgbo, depth, acc, B);
}

// round 13
// speedup vs baseline: 1.0989x; 1.0989x over previous
#include <cuda_runtime.h>
#include <math.h>

#define NS 64          // coarse samples
#define NF 128         // fine samples
#define NC 192         // combined
#define RPB 16         // rays per block (16-lane subwarp per ray)
#define FULL 0xffffffffu

// #{k in [0,128) : u_k < x}, u_k = 0.05 + k * (0.9/127)
__device__ __forceinline__ int count_u(float x) {
    int c = __float2int_ru((x - 0.05f) * (127.0f / 0.9f));
    return min(max(c, 0), NF);
}

__device__ __forceinline__ unsigned long long pack2(float lo, float hi) {
    unsigned long long r;
    asm("mov.b64 %0, {%1, %2};" : "=l"(r) : "f"(lo), "f"(hi));
    return r;
}
__device__ __forceinline__ void unpack2(unsigned long long v, float& lo, float& hi) {
    asm("mov.b64 {%0, %1}, %2;" : "=f"(lo), "=f"(hi) : "l"(v));
}
__device__ __forceinline__ unsigned long long addp(unsigned long long a, unsigned long long b) {
    unsigned long long r;
    asm("add.rn.f32x2 %0, %1, %2;" : "=l"(r) : "l"(a), "l"(b));
    return r;
}

__global__ __launch_bounds__(256, 8)
void pdf_sampler_kernel(const float* __restrict__ near_, const float* __restrict__ far_,
                        const float* __restrict__ density, const float* __restrict__ rgb,
                        float* __restrict__ zs_out, float* __restrict__ rgb_out,
                        float* __restrict__ depth_out, float* __restrict__ acc_out,
                        int B)
{
    __shared__ __align__(16) float  s_z[RPB][NC];        // staging; first 128B alias byte-S[]
    __shared__ __align__(16) float2 s_par[RPB][NS + 2];  // (cb, g) per interval, + tail

    const int sub = threadIdx.x >> 4;    // ray slot in block
    const int g   = threadIdx.x & 15;    // lane within 16-lane group
    const int ray = blockIdx.x * RPB + sub;
    if (ray >= B) return;

    const float nr = near_[ray];
    const float fr = far_[ray];
    const float delta = (fr - nr) * (1.0f / NS);

    // ---- density: 4 elems per lane (float4, coalesced) ----
    const float4 dvec = *reinterpret_cast<const float4*>(density + (size_t)ray * NS + 4 * g);
    const float e0 = dvec.x * delta;
    const float e1 = dvec.y * delta;
    const float e2 = dvec.z * delta;
    const float e3 = dvec.w * delta;

    // ---- 16-wide inclusive prefix sum of optical depth (quad per lane) ----
    const float tot = ((e0 + e1) + e2) + e3;
    float s = tot;
    #pragma unroll
    for (int off = 1; off < 16; off <<= 1) {
        float v = __shfl_up_sync(FULL, s, off, 16);
        if (g >= off) s += v;
    }
    const float excl = s - tot;          // cum optical depth before elem 4*g

    // weights chain: w_i = T_i * (1 - exp(-e_i)), T_{i+1} = T_i - w_i
    const float T0 = __expf(-excl);
    const float w0 = T0 * (1.0f - __expf(-e0));
    const float T1 = T0 - w0;
    const float w1 = T1 * (1.0f - __expf(-e1));
    const float T2 = T1 - w1;
    const float w2 = T2 * (1.0f - __expf(-e2));
    const float T3 = T2 - w2;
    const float w3 = T3 * (1.0f - __expf(-e3));
    const float T4 = T3 - w3;

    // analytic mids
    const float m0 = fmaf((float)(4 * g) + 0.5f, delta, nr);
    const float m1 = m0 + delta;
    const float m2 = m1 + delta;
    const float m3 = m2 + delta;

    // ---- rgb loads: 12 contiguous floats per lane (3x float4, 48B-aligned) ----
    const float* rrow = rgb + (size_t)ray * (NS * 3) + 12 * g;
    const float4 f0 = *reinterpret_cast<const float4*>(rrow + 0);  // r0 g0 b0 r1
    const float4 f1 = *reinterpret_cast<const float4*>(rrow + 4);  // g1 b1 r2 g2
    const float4 f2 = *reinterpret_cast<const float4*>(rrow + 8);  // b2 r3 g3 b3

    // ---- reductions (packed f32x2 butterflies, width 16) ----
    const float rs = w0 * f0.x + w1 * f0.w + w2 * f1.z + w3 * f2.y;
    const float gs = w0 * f0.y + w1 * f1.x + w2 * f1.w + w3 * f2.z;
    const float bs = w0 * f0.z + w1 * f1.y + w2 * f2.x + w3 * f2.w;
    const float ds = w0 * m0 + w1 * m1 + w2 * m2 + w3 * m3;
    unsigned long long q0 = pack2(rs, gs);
    unsigned long long q1 = pack2(bs, ds);
    #pragma unroll
    for (int off = 8; off >= 1; off >>= 1) {
        q0 = addp(q0, __shfl_xor_sync(FULL, q0, off, 16));
        q1 = addp(q1, __shfl_xor_sync(FULL, q1, off, 16));
    }

    // total weight: exp(-ctot) is group-lane-15's T4
    const float wsum = 1.0f - __shfl_sync(FULL, T4, 15, 16);
    const float inv  = __fdividef(1.0f, wsum + 1e-6f);

    // normalized cdf at this lane's four positions
    const float cA = (1.0f - T1) * inv;   // cdf[4g]
    const float cB = (1.0f - T2) * inv;   // cdf[4g+1]
    const float cC = (1.0f - T3) * inv;   // cdf[4g+2]
    const float cD = (1.0f - T4) * inv;   // cdf[4g+3]
    float cprev = __shfl_up_sync(FULL, cD, 1, 16);   // cdf[4g-1]
    if (g == 0) cprev = 0.0f;

    // interval ends in fine-sample index space
    const int k1 = count_u(cA);
    const int k2 = count_u(cB);
    const int k3 = count_u(cC);
    const int k4 = count_u(cD);
    int kS = __shfl_up_sync(FULL, k4, 1, 16);        // = count_u(cprev)
    if (g == 0) kS = 0;

    // per-interval affine params: z = fmaf(u - cb, gcoef, mids[pc-1])
    const float d0 = cA - cprev;
    const float g0c = (g == 0) ? 0.0f : ((d0 < 1e-5f) ? delta : __fdividef(delta, d0));
    const float d1 = cB - cA;
    const float g1c = (d1 < 1e-5f) ? delta : __fdividef(delta, d1);
    const float d2 = cC - cB;
    const float g2c = (d2 < 1e-5f) ? delta : __fdividef(delta, d2);
    const float d3 = cD - cC;
    const float g3c = (d3 < 1e-5f) ? delta : __fdividef(delta, d3);

    float* zw = s_z[sub];
    unsigned char* Sw = reinterpret_cast<unsigned char*>(zw);  // byte S[128] aliases staging
    float2* pw = s_par[sub];

    // ---- S init (8B/lane) + params (2x STS.128/lane, conflict-free) ----
    reinterpret_cast<unsigned long long*>(zw)[g] = 0ULL;
    reinterpret_cast<float4*>(pw)[2 * g]     = make_float4(cprev, g0c, cA, g1c);  // pw[4g],pw[4g+1]
    reinterpret_cast<float4*>(pw)[2 * g + 1] = make_float4(cB,    g2c, cC, g3c);  // pw[4g+2],pw[4g+3]
    if (g == 15) pw[NS] = make_float2(0.0f, 0.0f);   // tail p=64: z = mids[63]
    __syncwarp();
    // interval-start marks (nonempty intervals have distinct starts; bytes 0..64)
    if (kS < k1) Sw[kS] = (unsigned char)(4 * g);
    if (k1 < k2) Sw[k1] = (unsigned char)(4 * g + 1);
    if (k2 < k3) Sw[k2] = (unsigned char)(4 * g + 2);
    if (k3 < k4) Sw[k3] = (unsigned char)(4 * g + 3);
    if (g == 15 && k4 < NF) Sw[k4] = (unsigned char)NS;   // tail interval start
    __syncwarp();

    // ---- p(k) = inclusive max-scan of byte S (8 bytes per lane) ----
    const unsigned long long wrd = reinterpret_cast<const unsigned long long*>(zw)[g];
    int sb[8];
    int run = 0;
    #pragma unroll
    for (int j = 0; j < 8; ++j) {
        run = max(run, (int)((wrd >> (8 * j)) & 0xFFULL));
        sb[j] = run;
    }
    int m = run;
    #pragma unroll
    for (int off = 1; off < 16; off <<= 1) {
        int t = __shfl_up_sync(FULL, m, off, 16);
        if (g >= off) m = max(m, t);
    }
    int pex = __shfl_up_sync(FULL, m, 1, 16);
    if (g == 0) pex = 0;
    __syncwarp();   // S fully consumed; staging reuse begins

    // ---- balanced fine pass: 8 samples per lane, branch-free ----
    const float ustep = 0.9f / 127.0f;
    const float base  = nr - 0.5f * delta;       // mids[pc-1] = fmaf(pc, delta, base)
    #pragma unroll
    for (int j = 0; j < 8; ++j) {
        const int k = 8 * g + j;
        const int p = max(pex, sb[j]);
        const int pc = min(max(p, 1), NS);       // clamp(p,1,64)
        const float2 pr = pw[p];
        const float u  = fmaf((float)k, ustep, 0.05f);
        const float mb = fmaf((float)pc, delta, base);
        zw[k + pc] = fmaf(u - pr.x, pr.y, mb);   // slot = k + clamp(p,1,64)
    }

    // ---- mids: slot = i + (# fine strictly before mid i) ----
    const int i0 = 4 * g;
    zw[(i0 == 0) ? 0 : (i0 + k1)] = m0;
    zw[i0 + 1 + k2] = m1;
    zw[i0 + 2 + k3] = m2;
    zw[i0 + 3 + k4] = m3;
    __syncwarp();

    // ---- coalesced vectorized write of the merged row (3 full float4 passes) ----
    float4* zv = reinterpret_cast<float4*>(zs_out + (size_t)ray * NC);
    const float4* sv = reinterpret_cast<const float4*>(zw);
    zv[g]      = sv[g];
    zv[16 + g] = sv[16 + g];
    zv[32 + g] = sv[32 + g];

    // ---- scalar outputs, distributed (all lanes hold reduced values) ----
    if (g < 5) {
        float rrs, rgs, rbs, rds;
        unpack2(q0, rrs, rgs);
        unpack2(q1, rbs, rds);
        if (g < 3) {
            const float val = (g == 0) ? rrs : (g == 1) ? rgs : rbs;
            rgb_out[(size_t)ray * 3 + g] = val;
        } else if (g == 3) {
            depth_out[ray] = __fdividef(rds, wsum + 1e-8f);
        } else {
            acc_out[ray] = wsum;
        }
    }
}

extern "C" void kernel_launch(void* const* d_in, const int* in_sizes, int n_in,
                              void* d_out, int out_size)
{
    const float* near_   = (const float*)d_in[0];
    const float* far_    = (const float*)d_in[1];
    const float* density = (const float*)d_in[2];
    const float* rgb     = (const float*)d_in[3];
    const int B = in_sizes[0];

    float* out   = (float*)d_out;
    float* zs    = out;                       // B * 192
    float* rgbo  = zs + (size_t)B * NC;       // B * 3
    float* depth = rgbo + (size_t)B * 3;      // B
    float* acc   = depth + B;                 // B

    const int blocks = (B + RPB - 1) / RPB;
    pdf_sampler_kernel<<<blocks, 256>>>(near_, far_, density, rgb,
                                        zs, rgbo, depth, acc, B);
}